// round 7
// baseline (speedup 1.0000x reference)
#include <cuda_runtime.h>
#include <cstdint>

#define N_NODES   50000
#define EMB       320
#define HID       64
#define NH        128
#define N_EDGES   400000
#define BK        16
#define NCHUNK    (EMB / BK)   // 20

typedef unsigned long long ull;

// Scratch (no allocations allowed)
__device__ __align__(16) float g_P[N_NODES * NH];
__device__ __align__(16) float g_w[N_EDGES];
__device__ __align__(16) float g_cvec[HID];
__device__ int g_idx64;

// packed f32x2 FMA: d.lo += a.lo*b.lo ; d.hi += a.hi*b.hi
__device__ __forceinline__ void ffma2(ull& d, ull a, ull b) {
    asm("fma.rn.f32x2 %0, %1, %2, %0;" : "+l"(d) : "l"(a), "l"(b));
}
__device__ __forceinline__ ull dup_f32(float x) {
    unsigned u = __float_as_uint(x);
    return (ull)u | ((ull)u << 32);
}

// ---------------------------------------------------------------------------
// Kernel 0: detect edge_index element width (int32 vs int64, little-endian).
// ---------------------------------------------------------------------------
__global__ void detect_kernel(const int* __restrict__ ei_raw) {
    int is64 = 1;
    #pragma unroll
    for (int i = 0; i < 32; i++)
        if (ei_raw[2 * i + 1] != 0) { is64 = 0; break; }
    g_idx64 = is64;
}

// ---------------------------------------------------------------------------
// Kernel 1: fp32 SGEMM with packed fma.rn.f32x2 (FFMA2).
//   P[v,0:64]  = embed[v] @ W1[0:320,:]
//   P[v,64:128]= embed[v] @ W1[320:640,:]
// Block 128x128, 256 thr, warp tile 32x64, micro 8x8, BK=16.
// A stored in smem as duplicated {a,a} 64-bit pairs; B natural (adjacent-n
// floats form the f32x2 pair). Inner loop: 6 LDS.128 + 32 FFMA2 per k.
// ---------------------------------------------------------------------------
__global__ __launch_bounds__(256, 2) void gemm_kernel(const float* __restrict__ embed,
                                                      const float* __restrict__ W1) {
    __shared__ __align__(16) ull   As2[BK][128];   // [k][m] duplicated pairs (16 KB)
    __shared__ __align__(16) float Bs[BK][128];    // [k][n] natural (8 KB)

    const int tid  = threadIdx.x;
    const int wid  = tid >> 5;
    const int lane = tid & 31;
    const int wm   = wid & 3;        // warp row   -> m offset wm*32
    const int wn   = wid >> 2;       // warp col   -> n offset wn*64
    const int tm   = lane & 3;       // thread row -> +tm*4 (and +16)
    const int tn   = lane >> 2;      // thread col -> +tn*4 (and +32)
    const int m0   = blockIdx.x * 128;
    const int rbase = wm * 32 + tm * 4;
    const int cbase = wn * 64 + tn * 4;

    // A loader: row am, k-offset ak (8 k-values per thread)
    const int am = tid >> 1;
    const int ak = (tid & 1) * 8;
    const int a_gm = m0 + am;
    // B loader: float4 col bn4, k row bk (2 k-rows per thread)
    const int bn4 = tid & 31;
    const int bk  = tid >> 5;
    const int bhalf = bn4 >> 4;
    const int bcol  = (bn4 & 15) * 4;
    const long long brow_base = (long long)bhalf * 320;

    float4 rA0, rA1, rB0, rB1;
    ull acc[8][4];
    #pragma unroll
    for (int i = 0; i < 8; i++)
        #pragma unroll
        for (int j = 0; j < 4; j++) acc[i][j] = 0ull;

    auto loadA = [&](int k0, float4& r0, float4& r1) {
        if (a_gm < N_NODES) {
            const float* p = &embed[(size_t)a_gm * EMB + k0 + ak];
            r0 = *reinterpret_cast<const float4*>(p);
            r1 = *reinterpret_cast<const float4*>(p + 4);
        } else {
            r0 = make_float4(0.f, 0.f, 0.f, 0.f);
            r1 = r0;
        }
    };
    auto loadB = [&](int k0, float4& r0, float4& r1) {
        r0 = *reinterpret_cast<const float4*>(&W1[(brow_base + k0 + bk) * 64 + bcol]);
        r1 = *reinterpret_cast<const float4*>(&W1[(brow_base + k0 + bk + 8) * 64 + bcol]);
    };
    auto stsA = [&](const float4& r0, const float4& r1) {
        As2[ak + 0][am] = dup_f32(r0.x); As2[ak + 1][am] = dup_f32(r0.y);
        As2[ak + 2][am] = dup_f32(r0.z); As2[ak + 3][am] = dup_f32(r0.w);
        As2[ak + 4][am] = dup_f32(r1.x); As2[ak + 5][am] = dup_f32(r1.y);
        As2[ak + 6][am] = dup_f32(r1.z); As2[ak + 7][am] = dup_f32(r1.w);
    };
    auto stsB = [&](const float4& r0, const float4& r1) {
        *reinterpret_cast<float4*>(&Bs[bk][bn4 * 4])     = r0;
        *reinterpret_cast<float4*>(&Bs[bk + 8][bn4 * 4]) = r1;
    };

    loadA(0, rA0, rA1);
    loadB(0, rB0, rB1);
    stsA(rA0, rA1);
    stsB(rB0, rB1);
    __syncthreads();

    for (int c = 0; c < NCHUNK; c++) {
        if (c + 1 < NCHUNK) {
            loadA((c + 1) * BK, rA0, rA1);
            loadB((c + 1) * BK, rB0, rB1);
        }

        #pragma unroll
        for (int k = 0; k < BK; k++) {
            // A: 8 duplicated pairs (rows rbase..+3, rbase+16..+19) via 4 LDS.128
            ulonglong2 pa0 = *reinterpret_cast<const ulonglong2*>(&As2[k][rbase]);
            ulonglong2 pa1 = *reinterpret_cast<const ulonglong2*>(&As2[k][rbase + 2]);
            ulonglong2 pa2 = *reinterpret_cast<const ulonglong2*>(&As2[k][rbase + 16]);
            ulonglong2 pa3 = *reinterpret_cast<const ulonglong2*>(&As2[k][rbase + 18]);
            // B: 4 natural pairs (cols cbase..+3, cbase+32..+35) via 2 LDS.128
            ulonglong2 pb0 = *reinterpret_cast<const ulonglong2*>(&Bs[k][cbase]);
            ulonglong2 pb1 = *reinterpret_cast<const ulonglong2*>(&Bs[k][cbase + 32]);
            ull a[8] = {pa0.x, pa0.y, pa1.x, pa1.y, pa2.x, pa2.y, pa3.x, pa3.y};
            ull b[4] = {pb0.x, pb0.y, pb1.x, pb1.y};
            #pragma unroll
            for (int i = 0; i < 8; i++)
                #pragma unroll
                for (int j = 0; j < 4; j++)
                    ffma2(acc[i][j], a[i], b[j]);
        }
        __syncthreads();
        if (c + 1 < NCHUNK) {
            stsA(rA0, rA1);
            stsB(rB0, rB1);
            __syncthreads();
        }
    }

    // ---- epilogue: acc pairs are adjacent columns -> direct 16B stores ----
    #pragma unroll
    for (int i = 0; i < 8; i++) {
        int gm = m0 + rbase + (i & 3) + (i >> 2) * 16;
        if (gm < N_NODES) {
            ull* dst = reinterpret_cast<ull*>(&g_P[(size_t)gm * NH + cbase]);
            *reinterpret_cast<ulonglong2*>(dst)     = make_ulonglong2(acc[i][0], acc[i][1]);
            *reinterpret_cast<ulonglong2*>(dst + 16) = make_ulonglong2(acc[i][2], acc[i][3]);
        }
    }
}

// ---------------------------------------------------------------------------
// Kernel 2: cvec[j] = b1[j] + embed[node_id] @ W1[640:960, j]   (exact fp32)
// ---------------------------------------------------------------------------
__global__ void cvec_kernel(const float* __restrict__ embed,
                            const float* __restrict__ W1,
                            const float* __restrict__ b1,
                            const int*   __restrict__ nid) {
    int j = threadIdx.x;
    int n = nid[0];
    const float* er = &embed[(size_t)n * EMB];
    float s = b1[j];
    #pragma unroll 4
    for (int k = 0; k < EMB; k++)
        s = fmaf(er[k], W1[(640 + k) * 64 + j], s);
    g_cvec[j] = s;
}

// ---------------------------------------------------------------------------
// Kernel 3a: gather + dot only (no transcendentals). 8 lanes/edge, 4 edges/warp.
//   g_w[e] = relu(P[col][0:64] + P[row][64:128] + cvec) . W2
// ---------------------------------------------------------------------------
__global__ __launch_bounds__(256) void edge_dot_kernel(const void* __restrict__ ei_raw,
                                                       const float* __restrict__ W2) {
    const int lane = threadIdx.x & 31;
    const int sub  = lane >> 3;           // edge slot within warp (0..3)
    const int j8   = lane & 7;            // dim group: 8 floats [j8*8, j8*8+8)
    const int warpGlobal = (blockIdx.x * blockDim.x + threadIdx.x) >> 5;
    const int nWarps = (gridDim.x * blockDim.x) >> 5;

    const float4 cv0 = *reinterpret_cast<const float4*>(&g_cvec[j8 * 8]);
    const float4 cv1 = *reinterpret_cast<const float4*>(&g_cvec[j8 * 8 + 4]);
    const float4 w20 = *reinterpret_cast<const float4*>(&W2[j8 * 8]);
    const float4 w21 = *reinterpret_cast<const float4*>(&W2[j8 * 8 + 4]);
    const int is64 = g_idx64;
    const long long* e64 = (const long long*)ei_raw;
    const int*       e32 = (const int*)ei_raw;

    for (int e = warpGlobal * 4 + sub; e < N_EDGES; e += nWarps * 4) {
        int col, row;
        if (is64) { col = (int)e64[e]; row = (int)e64[N_EDGES + e]; }
        else      { col = e32[e];      row = e32[N_EDGES + e]; }

        const float* Pc = &g_P[(size_t)col * NH + j8 * 8];
        const float* Pr = &g_P[(size_t)row * NH + 64 + j8 * 8];
        float4 a0 = *reinterpret_cast<const float4*>(Pc);
        float4 a1 = *reinterpret_cast<const float4*>(Pc + 4);
        float4 b0 = *reinterpret_cast<const float4*>(Pr);
        float4 b1 = *reinterpret_cast<const float4*>(Pr + 4);

        float p;
        p  = fmaxf(a0.x + b0.x + cv0.x, 0.f) * w20.x;
        p  = fmaf(fmaxf(a0.y + b0.y + cv0.y, 0.f), w20.y, p);
        p  = fmaf(fmaxf(a0.z + b0.z + cv0.z, 0.f), w20.z, p);
        p  = fmaf(fmaxf(a0.w + b0.w + cv0.w, 0.f), w20.w, p);
        p  = fmaf(fmaxf(a1.x + b1.x + cv1.x, 0.f), w21.x, p);
        p  = fmaf(fmaxf(a1.y + b1.y + cv1.y, 0.f), w21.y, p);
        p  = fmaf(fmaxf(a1.z + b1.z + cv1.z, 0.f), w21.z, p);
        p  = fmaf(fmaxf(a1.w + b1.w + cv1.w, 0.f), w21.w, p);

        p += __shfl_xor_sync(0xffffffffu, p, 4);
        p += __shfl_xor_sync(0xffffffffu, p, 2);
        p += __shfl_xor_sync(0xffffffffu, p, 1);

        if (j8 == 0) g_w[e] = p;
    }
}

// ---------------------------------------------------------------------------
// Kernel 3b: dense gate pass, fully vectorized transcendentals.
// tmp==1 fast path: sigmoid(log(e/(1-e)) + w) = e / (e + exp(-w)*(1-e)).
// ---------------------------------------------------------------------------
__global__ __launch_bounds__(256) void gate_kernel(const float* __restrict__ eps,
                                                   const float* __restrict__ tmp,
                                                   const float* __restrict__ b2,
                                                   float* __restrict__ out) {
    int i = blockIdx.x * blockDim.x + threadIdx.x;
    if (i * 4 >= N_EDGES) return;
    const float bias = 0.0001f, c1 = 1.f - 2.f * 0.0001f;
    float4 ev = *reinterpret_cast<const float4*>(&eps[i * 4]);
    float4 wv = *reinterpret_cast<const float4*>(&g_w[i * 4]);
    float t = tmp[0];
    float bb = b2[0];
    float e[4] = {fmaf(ev.x, c1, bias), fmaf(ev.y, c1, bias),
                  fmaf(ev.z, c1, bias), fmaf(ev.w, c1, bias)};
    float w[4] = {wv.x + bb, wv.y + bb, wv.z + bb, wv.w + bb};
    float o[4];
    if (t == 1.0f) {
        #pragma unroll
        for (int q = 0; q < 4; q++) {
            float s = __expf(-w[q]);
            o[q] = __fdividef(e[q], fmaf(s, 1.f - e[q], e[q]));
        }
    } else {
        float inv_t = __fdividef(1.f, t);
        #pragma unroll
        for (int q = 0; q < 4; q++) {
            float gate = (__logf(e[q]) - __logf(1.f - e[q]) + w[q]) * inv_t;
            o[q] = __fdividef(1.f, 1.f + __expf(-gate));
        }
    }
    *reinterpret_cast<float4*>(&out[i * 4]) = make_float4(o[0], o[1], o[2], o[3]);
}

// ---------------------------------------------------------------------------
// Inputs: 0:x 1:embed 2:edge_index 3:node_id 4:tmp 5:eps 6:W1 7:b1 8:W2 9:b2
// ---------------------------------------------------------------------------
extern "C" void kernel_launch(void* const* d_in, const int* in_sizes, int n_in,
                              void* d_out, int out_size) {
    const float* embed = (const float*)d_in[1];
    const void*  ei    = d_in[2];
    const int*   nid   = (const int*)d_in[3];
    const float* tmp   = (const float*)d_in[4];
    const float* eps   = (const float*)d_in[5];
    const float* W1    = (const float*)d_in[6];
    const float* b1    = (const float*)d_in[7];
    const float* W2    = (const float*)d_in[8];
    const float* b2    = (const float*)d_in[9];
    float* out = (float*)d_out;

    detect_kernel<<<1, 1>>>((const int*)ei);
    gemm_kernel<<<(N_NODES + 127) / 128, 256>>>(embed, W1);
    cvec_kernel<<<1, 64>>>(embed, W1, b1, nid);
    edge_dot_kernel<<<1184, 256>>>(ei, W2);
    gate_kernel<<<(N_EDGES / 4 + 255) / 256, 256>>>(eps, tmp, b2, out);
}

// round 8
// speedup vs baseline: 1.1026x; 1.1026x over previous
#include <cuda_runtime.h>
#include <cuda_bf16.h>
#include <mma.h>
#include <cstdint>
using namespace nvcuda;

#define N_NODES   50000
#define EMB       320
#define HID       64
#define NH        128
#define N_EDGES   400000
#define BK        16
#define NCHUNK    (EMB / BK)   // 20
#define NTILES    391          // ceil(50000/128)
#define NW_TILES  144          // tiles handled by the wmma (tensor-pipe) path

#define AP 40    // wmma A smem pitch (bf16)
#define BP 136   // wmma B smem pitch (bf16)

// Scratch (no allocations allowed)
__device__ __align__(16) float g_P[N_NODES * NH];
__device__ __align__(16) float g_w[N_EDGES];
__device__ __align__(16) float g_cvec[HID];
__device__ int g_idx64;

// ---------------------------------------------------------------------------
// Kernel 0: detect edge_index element width (int32 vs int64, little-endian).
// ---------------------------------------------------------------------------
__global__ void detect_kernel(const int* __restrict__ ei_raw) {
    int is64 = 1;
    #pragma unroll
    for (int i = 0; i < 32; i++)
        if (ei_raw[2 * i + 1] != 0) { is64 = 0; break; }
    g_idx64 = is64;
}

// ---------------------------------------------------------------------------
// Kernel 1: HYBRID GEMM.  P[v,0:64]=embed[v]@W1[0:320,:], P[v,64:128]=...
// Blocks < NW_TILES: bf16 3-term wmma path (tensor pipe, R4-verified).
// Blocks >= NW_TILES: fp32 FFMA path (fma pipe, R6-verified).
// 2 blocks/SM co-resident -> both pipes busy on the same SM.
// ---------------------------------------------------------------------------
struct WmmaSmem {
    __nv_bfloat16 Ah[128][AP], Al[128][AP];   // 2 x 10240 B
    __nv_bfloat16 Bh[32][BP],  Bl[32][BP];    // 2 x 8704 B
};
struct FfmaSmem {
    float As[BK][128];   // 8 KB
    float Bs[BK][128];   // 8 KB
};

__global__ __launch_bounds__(256, 2) void gemm_hybrid(const float* __restrict__ embed,
                                                      const float* __restrict__ W1) {
    __shared__ __align__(16) char smem_u[sizeof(WmmaSmem)];   // union (37.9 KB)

    const int tid  = threadIdx.x;
    const int wid  = tid >> 5;
    const int lane = tid & 31;
    const int m0   = blockIdx.x * 128;

    if (blockIdx.x < NW_TILES) {
        // ================= wmma bf16 3-term path =================
        WmmaSmem& S = *reinterpret_cast<WmmaSmem*>(smem_u);
        const int warp_m = wid & 1;
        const int warp_n = wid >> 1;

        wmma::fragment<wmma::accumulator, 16, 16, 16, float> acc[4][2];
        #pragma unroll
        for (int i = 0; i < 4; i++)
            #pragma unroll
            for (int j = 0; j < 2; j++)
                wmma::fill_fragment(acc[i][j], 0.f);

        for (int k0 = 0; k0 < EMB; k0 += 32) {
            for (int it = tid; it < 128 * 8; it += 256) {
                int r = it >> 3, q = it & 7;
                int gm = m0 + r;
                float4 v = make_float4(0.f, 0.f, 0.f, 0.f);
                if (gm < N_NODES)
                    v = *reinterpret_cast<const float4*>(&embed[(size_t)gm * EMB + k0 + q * 4]);
                float a[4] = {v.x, v.y, v.z, v.w};
                __nv_bfloat16 h[4], l[4];
                #pragma unroll
                for (int i = 0; i < 4; i++) {
                    h[i] = __float2bfloat16(a[i]);
                    l[i] = __float2bfloat16(a[i] - __bfloat162float(h[i]));
                }
                *reinterpret_cast<uint2*>(&S.Ah[r][q * 4]) = *reinterpret_cast<uint2*>(h);
                *reinterpret_cast<uint2*>(&S.Al[r][q * 4]) = *reinterpret_cast<uint2*>(l);
            }
            for (int it = tid; it < 1024; it += 256) {
                int j4 = it & 15, half = (it >> 4) & 1, k = it >> 5;
                float4 v = *reinterpret_cast<const float4*>(&W1[(half * 320 + k0 + k) * 64 + j4 * 4]);
                float b[4] = {v.x, v.y, v.z, v.w};
                __nv_bfloat16 h[4], l[4];
                #pragma unroll
                for (int i = 0; i < 4; i++) {
                    h[i] = __float2bfloat16(b[i]);
                    l[i] = __float2bfloat16(b[i] - __bfloat162float(h[i]));
                }
                *reinterpret_cast<uint2*>(&S.Bh[k][half * 64 + j4 * 4]) = *reinterpret_cast<uint2*>(h);
                *reinterpret_cast<uint2*>(&S.Bl[k][half * 64 + j4 * 4]) = *reinterpret_cast<uint2*>(l);
            }
            __syncthreads();

            #pragma unroll
            for (int ks = 0; ks < 2; ks++) {
                wmma::fragment<wmma::matrix_b, 16, 16, 16, __nv_bfloat16, wmma::row_major> bh[2], bl[2];
                #pragma unroll
                for (int j = 0; j < 2; j++) {
                    wmma::load_matrix_sync(bh[j], &S.Bh[ks * 16][warp_n * 32 + j * 16], BP);
                    wmma::load_matrix_sync(bl[j], &S.Bl[ks * 16][warp_n * 32 + j * 16], BP);
                }
                #pragma unroll
                for (int i = 0; i < 4; i++) {
                    wmma::fragment<wmma::matrix_a, 16, 16, 16, __nv_bfloat16, wmma::row_major> fah, fal;
                    wmma::load_matrix_sync(fah, &S.Ah[warp_m * 64 + i * 16][ks * 16], AP);
                    wmma::load_matrix_sync(fal, &S.Al[warp_m * 64 + i * 16][ks * 16], AP);
                    #pragma unroll
                    for (int j = 0; j < 2; j++) {
                        wmma::mma_sync(acc[i][j], fah, bh[j], acc[i][j]);
                        wmma::mma_sync(acc[i][j], fah, bl[j], acc[i][j]);
                        wmma::mma_sync(acc[i][j], fal, bh[j], acc[i][j]);
                    }
                }
            }
            __syncthreads();
        }

        #pragma unroll
        for (int i = 0; i < 4; i++) {
            int gm = m0 + warp_m * 64 + i * 16;
            if (gm < N_NODES) {
                #pragma unroll
                for (int j = 0; j < 2; j++)
                    wmma::store_matrix_sync(&g_P[(size_t)gm * NH + warp_n * 32 + j * 16],
                                            acc[i][j], NH, wmma::mem_row_major);
            }
        }
    } else {
        // ================= fp32 FFMA path (R6) =================
        FfmaSmem& S = *reinterpret_cast<FfmaSmem*>(smem_u);
        const int wm = wid & 3;
        const int wn = wid >> 2;
        const int tm = lane & 3;
        const int tn = lane >> 2;

        const int am = tid >> 1;
        const int ak = (tid & 1) * 8;
        const int a_gm = m0 + am;
        const int bn4 = tid & 31;
        const int bk  = tid >> 5;
        const int bhalf = bn4 >> 4;
        const int bcol  = (bn4 & 15) * 4;
        const long long brow_base = (long long)bhalf * 320;

        float4 rA0, rA1, rB0, rB1;
        float acc[8][8];
        #pragma unroll
        for (int i = 0; i < 8; i++)
            #pragma unroll
            for (int j = 0; j < 8; j++) acc[i][j] = 0.f;

        auto loadA = [&](int k0, float4& r0, float4& r1) {
            if (a_gm < N_NODES) {
                const float* p = &embed[(size_t)a_gm * EMB + k0 + ak];
                r0 = *reinterpret_cast<const float4*>(p);
                r1 = *reinterpret_cast<const float4*>(p + 4);
            } else {
                r0 = make_float4(0.f, 0.f, 0.f, 0.f);
                r1 = r0;
            }
        };
        auto loadB = [&](int k0, float4& r0, float4& r1) {
            r0 = *reinterpret_cast<const float4*>(&W1[(brow_base + k0 + bk) * 64 + bcol]);
            r1 = *reinterpret_cast<const float4*>(&W1[(brow_base + k0 + bk + 8) * 64 + bcol]);
        };
        auto stsA = [&](const float4& r0, const float4& r1) {
            S.As[ak + 0][am] = r0.x; S.As[ak + 1][am] = r0.y;
            S.As[ak + 2][am] = r0.z; S.As[ak + 3][am] = r0.w;
            S.As[ak + 4][am] = r1.x; S.As[ak + 5][am] = r1.y;
            S.As[ak + 6][am] = r1.z; S.As[ak + 7][am] = r1.w;
        };
        auto stsB = [&](const float4& r0, const float4& r1) {
            *reinterpret_cast<float4*>(&S.Bs[bk][bn4 * 4])     = r0;
            *reinterpret_cast<float4*>(&S.Bs[bk + 8][bn4 * 4]) = r1;
        };

        loadA(0, rA0, rA1);
        loadB(0, rB0, rB1);
        stsA(rA0, rA1);
        stsB(rB0, rB1);
        __syncthreads();

        for (int c = 0; c < NCHUNK; c++) {
            if (c + 1 < NCHUNK) {
                loadA((c + 1) * BK, rA0, rA1);
                loadB((c + 1) * BK, rB0, rB1);
            }
            #pragma unroll
            for (int k = 0; k < BK; k++) {
                float4 a0 = *reinterpret_cast<const float4*>(&S.As[k][wm * 32 + tm * 4]);
                float4 a1 = *reinterpret_cast<const float4*>(&S.As[k][wm * 32 + tm * 4 + 16]);
                float4 b0 = *reinterpret_cast<const float4*>(&S.Bs[k][wn * 64 + tn * 4]);
                float4 b1 = *reinterpret_cast<const float4*>(&S.Bs[k][wn * 64 + tn * 4 + 32]);
                float av[8] = {a0.x, a0.y, a0.z, a0.w, a1.x, a1.y, a1.z, a1.w};
                float bv[8] = {b0.x, b0.y, b0.z, b0.w, b1.x, b1.y, b1.z, b1.w};
                #pragma unroll
                for (int i = 0; i < 8; i++)
                    #pragma unroll
                    for (int j = 0; j < 8; j++)
                        acc[i][j] = fmaf(av[i], bv[j], acc[i][j]);
            }
            __syncthreads();
            if (c + 1 < NCHUNK) {
                stsA(rA0, rA1);
                stsB(rB0, rB1);
                __syncthreads();
            }
        }

        #pragma unroll
        for (int i = 0; i < 8; i++) {
            int gm = m0 + wm * 32 + tm * 4 + (i & 3) + (i >> 2) * 16;
            if (gm < N_NODES) {
                float* dst = &g_P[(size_t)gm * NH + wn * 64 + tn * 4];
                *reinterpret_cast<float4*>(dst)      = make_float4(acc[i][0], acc[i][1], acc[i][2], acc[i][3]);
                *reinterpret_cast<float4*>(dst + 32) = make_float4(acc[i][4], acc[i][5], acc[i][6], acc[i][7]);
            }
        }
    }
}

// ---------------------------------------------------------------------------
// Kernel 2: cvec[j] = b1[j] + embed[node_id] @ W1[640:960, j]   (exact fp32)
// ---------------------------------------------------------------------------
__global__ void cvec_kernel(const float* __restrict__ embed,
                            const float* __restrict__ W1,
                            const float* __restrict__ b1,
                            const int*   __restrict__ nid) {
    int j = threadIdx.x;
    int n = nid[0];
    const float* er = &embed[(size_t)n * EMB];
    float s = b1[j];
    #pragma unroll 4
    for (int k = 0; k < EMB; k++)
        s = fmaf(er[k], W1[(640 + k) * 64 + j], s);
    g_cvec[j] = s;
}

// ---------------------------------------------------------------------------
// Kernel 3a: gather + dot (no transcendentals). 8 lanes/edge, 4 edges/warp.
// ---------------------------------------------------------------------------
__global__ __launch_bounds__(256) void edge_dot_kernel(const void* __restrict__ ei_raw,
                                                       const float* __restrict__ W2) {
    const int lane = threadIdx.x & 31;
    const int sub  = lane >> 3;
    const int j8   = lane & 7;
    const int warpGlobal = (blockIdx.x * blockDim.x + threadIdx.x) >> 5;
    const int nWarps = (gridDim.x * blockDim.x) >> 5;

    const float4 cv0 = *reinterpret_cast<const float4*>(&g_cvec[j8 * 8]);
    const float4 cv1 = *reinterpret_cast<const float4*>(&g_cvec[j8 * 8 + 4]);
    const float4 w20 = *reinterpret_cast<const float4*>(&W2[j8 * 8]);
    const float4 w21 = *reinterpret_cast<const float4*>(&W2[j8 * 8 + 4]);
    const int is64 = g_idx64;
    const long long* e64 = (const long long*)ei_raw;
    const int*       e32 = (const int*)ei_raw;

    for (int e = warpGlobal * 4 + sub; e < N_EDGES; e += nWarps * 4) {
        int col, row;
        if (is64) { col = (int)e64[e]; row = (int)e64[N_EDGES + e]; }
        else      { col = e32[e];      row = e32[N_EDGES + e]; }

        const float* Pc = &g_P[(size_t)col * NH + j8 * 8];
        const float* Pr = &g_P[(size_t)row * NH + 64 + j8 * 8];
        float4 a0 = *reinterpret_cast<const float4*>(Pc);
        float4 a1 = *reinterpret_cast<const float4*>(Pc + 4);
        float4 b0 = *reinterpret_cast<const float4*>(Pr);
        float4 b1 = *reinterpret_cast<const float4*>(Pr + 4);

        float p;
        p  = fmaxf(a0.x + b0.x + cv0.x, 0.f) * w20.x;
        p  = fmaf(fmaxf(a0.y + b0.y + cv0.y, 0.f), w20.y, p);
        p  = fmaf(fmaxf(a0.z + b0.z + cv0.z, 0.f), w20.z, p);
        p  = fmaf(fmaxf(a0.w + b0.w + cv0.w, 0.f), w20.w, p);
        p  = fmaf(fmaxf(a1.x + b1.x + cv1.x, 0.f), w21.x, p);
        p  = fmaf(fmaxf(a1.y + b1.y + cv1.y, 0.f), w21.y, p);
        p  = fmaf(fmaxf(a1.z + b1.z + cv1.z, 0.f), w21.z, p);
        p  = fmaf(fmaxf(a1.w + b1.w + cv1.w, 0.f), w21.w, p);

        p += __shfl_xor_sync(0xffffffffu, p, 4);
        p += __shfl_xor_sync(0xffffffffu, p, 2);
        p += __shfl_xor_sync(0xffffffffu, p, 1);

        if (j8 == 0) g_w[e] = p;
    }
}

// ---------------------------------------------------------------------------
// Kernel 3b: dense gate pass (tmp==1 fast path: no logs).
// ---------------------------------------------------------------------------
__global__ __launch_bounds__(256) void gate_kernel(const float* __restrict__ eps,
                                                   const float* __restrict__ tmp,
                                                   const float* __restrict__ b2,
                                                   float* __restrict__ out) {
    int i = blockIdx.x * blockDim.x + threadIdx.x;
    if (i * 4 >= N_EDGES) return;
    const float bias = 0.0001f, c1 = 1.f - 2.f * 0.0001f;
    float4 ev = *reinterpret_cast<const float4*>(&eps[i * 4]);
    float4 wv = *reinterpret_cast<const float4*>(&g_w[i * 4]);
    float t = tmp[0];
    float bb = b2[0];
    float e[4] = {fmaf(ev.x, c1, bias), fmaf(ev.y, c1, bias),
                  fmaf(ev.z, c1, bias), fmaf(ev.w, c1, bias)};
    float w[4] = {wv.x + bb, wv.y + bb, wv.z + bb, wv.w + bb};
    float o[4];
    if (t == 1.0f) {
        #pragma unroll
        for (int q = 0; q < 4; q++) {
            float s = __expf(-w[q]);
            o[q] = __fdividef(e[q], fmaf(s, 1.f - e[q], e[q]));
        }
    } else {
        float inv_t = __fdividef(1.f, t);
        #pragma unroll
        for (int q = 0; q < 4; q++) {
            float gate = (__logf(e[q]) - __logf(1.f - e[q]) + w[q]) * inv_t;
            o[q] = __fdividef(1.f, 1.f + __expf(-gate));
        }
    }
    *reinterpret_cast<float4*>(&out[i * 4]) = make_float4(o[0], o[1], o[2], o[3]);
}

// ---------------------------------------------------------------------------
// Inputs: 0:x 1:embed 2:edge_index 3:node_id 4:tmp 5:eps 6:W1 7:b1 8:W2 9:b2
// ---------------------------------------------------------------------------
extern "C" void kernel_launch(void* const* d_in, const int* in_sizes, int n_in,
                              void* d_out, int out_size) {
    const float* embed = (const float*)d_in[1];
    const void*  ei    = d_in[2];
    const int*   nid   = (const int*)d_in[3];
    const float* tmp   = (const float*)d_in[4];
    const float* eps   = (const float*)d_in[5];
    const float* W1    = (const float*)d_in[6];
    const float* b1    = (const float*)d_in[7];
    const float* W2    = (const float*)d_in[8];
    const float* b2    = (const float*)d_in[9];
    float* out = (float*)d_out;

    detect_kernel<<<1, 1>>>((const int*)ei);
    gemm_hybrid<<<NTILES, 256>>>(embed, W1);
    cvec_kernel<<<1, 64>>>(embed, W1, b1, nid);
    edge_dot_kernel<<<1184, 256>>>(ei, W2);
    gate_kernel<<<(N_EDGES / 4 + 255) / 256, 256>>>(eps, tmp, b2, out);
}

// round 9
// speedup vs baseline: 1.2686x; 1.1506x over previous
#include <cuda_runtime.h>
#include <cuda_bf16.h>
#include <mma.h>
#include <cstdint>
using namespace nvcuda;

#define N_NODES   50000
#define EMB       320
#define HID       64
#define NH        128
#define N_EDGES   400000
#define NTILES    391          // ceil(50000/128)

#define AP 40    // A smem pitch (bf16)
#define BP 136   // B smem pitch (bf16)

// Scratch (no allocations allowed)
__device__ __align__(16) float g_P[N_NODES * NH];
__device__ __align__(16) float g_w[N_EDGES];
__device__ __align__(16) float g_cvec[HID];
__device__ __align__(16) __nv_bfloat16 g_Eh[N_NODES * EMB];   // 32 MB
__device__ __align__(16) __nv_bfloat16 g_El[N_NODES * EMB];   // 32 MB
__device__ __align__(16) __nv_bfloat16 g_W1h[640 * 64];
__device__ __align__(16) __nv_bfloat16 g_W1l[640 * 64];
__device__ int g_idx64;

// ---------------------------------------------------------------------------
// Kernel 0: detect edge_index element width (int32 vs int64, little-endian).
// ---------------------------------------------------------------------------
__global__ void detect_kernel(const int* __restrict__ ei_raw) {
    int is64 = 1;
    #pragma unroll
    for (int i = 0; i < 32; i++)
        if (ei_raw[2 * i + 1] != 0) { is64 = 0; break; }
    g_idx64 = is64;
}

// ---------------------------------------------------------------------------
// Kernel S: fp32 -> (hi, lo) bf16 split, dense.  4 floats / thread.
// ---------------------------------------------------------------------------
__global__ __launch_bounds__(256) void split_kernel(const float* __restrict__ src,
                                                    __nv_bfloat16* __restrict__ dh,
                                                    __nv_bfloat16* __restrict__ dl,
                                                    int n4) {
    int i = blockIdx.x * blockDim.x + threadIdx.x;
    if (i >= n4) return;
    float4 v = *reinterpret_cast<const float4*>(&src[i * 4]);
    float a[4] = {v.x, v.y, v.z, v.w};
    __nv_bfloat16 h[4], l[4];
    #pragma unroll
    for (int q = 0; q < 4; q++) {
        h[q] = __float2bfloat16(a[q]);
        l[q] = __float2bfloat16(a[q] - __bfloat162float(h[q]));
    }
    *reinterpret_cast<uint2*>(&dh[i * 4]) = *reinterpret_cast<uint2*>(h);
    *reinterpret_cast<uint2*>(&dl[i * 4]) = *reinterpret_cast<uint2*>(l);
}

// ---------------------------------------------------------------------------
// Kernel 1: wmma bf16 3-term GEMM, converts hoisted out (pure copy loader).
//   P[v,0:64]  = embed[v] @ W1[0:320,:]
//   P[v,64:128]= embed[v] @ W1[320:640,:]
// Block 128x128, 8 warps, warp tile 64x32 (4x2 frags), K chunks of 32.
// acc += Ah*Bh + Ah*Bl + Al*Bh  (missing Al*Bl ~ 2^-16 rel).
// ---------------------------------------------------------------------------
__global__ __launch_bounds__(256, 2) void gemm_kernel() {
    __shared__ __nv_bfloat16 Ah[128][AP], Al[128][AP];
    __shared__ __nv_bfloat16 Bh[32][BP],  Bl[32][BP];

    const int tid = threadIdx.x;
    const int wid = tid >> 5;
    const int warp_m = wid & 1;
    const int warp_n = wid >> 1;
    const int m0 = blockIdx.x * 128;

    wmma::fragment<wmma::accumulator, 16, 16, 16, float> acc[4][2];
    #pragma unroll
    for (int i = 0; i < 4; i++)
        #pragma unroll
        for (int j = 0; j < 2; j++)
            wmma::fill_fragment(acc[i][j], 0.f);

    for (int k0 = 0; k0 < EMB; k0 += 32) {
        // ---- A: 128 rows x 32 k, 512 uint4 per buffer; 2 hi + 2 lo per thread ----
        #pragma unroll
        for (int p = 0; p < 2; p++) {
            int it = tid + 256 * p;
            int r = it >> 2, q = it & 3;           // row, uint4-col (8 bf16)
            int gm = m0 + r;
            uint4 vh = make_uint4(0u, 0u, 0u, 0u), vl = vh;
            if (gm < N_NODES) {
                size_t off = (size_t)gm * EMB + k0 + q * 8;
                vh = *reinterpret_cast<const uint4*>(&g_Eh[off]);
                vl = *reinterpret_cast<const uint4*>(&g_El[off]);
            }
            *reinterpret_cast<uint4*>(&Ah[r][q * 8]) = vh;
            *reinterpret_cast<uint4*>(&Al[r][q * 8]) = vl;
        }
        // ---- B: 32 k x 128 n, 512 uint4 per buffer; 2 hi + 2 lo per thread ----
        #pragma unroll
        for (int p = 0; p < 2; p++) {
            int it = tid + 256 * p;
            int u4 = it & 7, half = (it >> 3) & 1, k = it >> 4;
            size_t off = (size_t)(half * 320 + k0 + k) * 64 + u4 * 8;
            *reinterpret_cast<uint4*>(&Bh[k][half * 64 + u4 * 8]) =
                *reinterpret_cast<const uint4*>(&g_W1h[off]);
            *reinterpret_cast<uint4*>(&Bl[k][half * 64 + u4 * 8]) =
                *reinterpret_cast<const uint4*>(&g_W1l[off]);
        }
        __syncthreads();

        #pragma unroll
        for (int ks = 0; ks < 2; ks++) {
            wmma::fragment<wmma::matrix_b, 16, 16, 16, __nv_bfloat16, wmma::row_major> bh[2], bl[2];
            #pragma unroll
            for (int j = 0; j < 2; j++) {
                wmma::load_matrix_sync(bh[j], &Bh[ks * 16][warp_n * 32 + j * 16], BP);
                wmma::load_matrix_sync(bl[j], &Bl[ks * 16][warp_n * 32 + j * 16], BP);
            }
            #pragma unroll
            for (int i = 0; i < 4; i++) {
                wmma::fragment<wmma::matrix_a, 16, 16, 16, __nv_bfloat16, wmma::row_major> fah, fal;
                wmma::load_matrix_sync(fah, &Ah[warp_m * 64 + i * 16][ks * 16], AP);
                wmma::load_matrix_sync(fal, &Al[warp_m * 64 + i * 16][ks * 16], AP);
                #pragma unroll
                for (int j = 0; j < 2; j++) {
                    wmma::mma_sync(acc[i][j], fah, bh[j], acc[i][j]);
                    wmma::mma_sync(acc[i][j], fah, bl[j], acc[i][j]);
                    wmma::mma_sync(acc[i][j], fal, bh[j], acc[i][j]);
                }
            }
        }
        __syncthreads();
    }

    #pragma unroll
    for (int i = 0; i < 4; i++) {
        int gm = m0 + warp_m * 64 + i * 16;
        if (gm < N_NODES) {
            #pragma unroll
            for (int j = 0; j < 2; j++)
                wmma::store_matrix_sync(&g_P[(size_t)gm * NH + warp_n * 32 + j * 16],
                                        acc[i][j], NH, wmma::mem_row_major);
        }
    }
}

// ---------------------------------------------------------------------------
// Kernel 2: cvec[j] = b1[j] + embed[node_id] @ W1[640:960, j]   (exact fp32)
// ---------------------------------------------------------------------------
__global__ void cvec_kernel(const float* __restrict__ embed,
                            const float* __restrict__ W1,
                            const float* __restrict__ b1,
                            const int*   __restrict__ nid) {
    int j = threadIdx.x;
    int n = nid[0];
    const float* er = &embed[(size_t)n * EMB];
    float s = b1[j];
    #pragma unroll 4
    for (int k = 0; k < EMB; k++)
        s = fmaf(er[k], W1[(640 + k) * 64 + j], s);
    g_cvec[j] = s;
}

// ---------------------------------------------------------------------------
// Kernel 3a: gather + dot (no transcendentals). 8 lanes/edge, 4 edges/warp.
// ---------------------------------------------------------------------------
__global__ __launch_bounds__(256) void edge_dot_kernel(const void* __restrict__ ei_raw,
                                                       const float* __restrict__ W2) {
    const int lane = threadIdx.x & 31;
    const int sub  = lane >> 3;
    const int j8   = lane & 7;
    const int warpGlobal = (blockIdx.x * blockDim.x + threadIdx.x) >> 5;
    const int nWarps = (gridDim.x * blockDim.x) >> 5;

    const float4 cv0 = *reinterpret_cast<const float4*>(&g_cvec[j8 * 8]);
    const float4 cv1 = *reinterpret_cast<const float4*>(&g_cvec[j8 * 8 + 4]);
    const float4 w20 = *reinterpret_cast<const float4*>(&W2[j8 * 8]);
    const float4 w21 = *reinterpret_cast<const float4*>(&W2[j8 * 8 + 4]);
    const int is64 = g_idx64;
    const long long* e64 = (const long long*)ei_raw;
    const int*       e32 = (const int*)ei_raw;

    for (int e = warpGlobal * 4 + sub; e < N_EDGES; e += nWarps * 4) {
        int col, row;
        if (is64) { col = (int)e64[e]; row = (int)e64[N_EDGES + e]; }
        else      { col = e32[e];      row = e32[N_EDGES + e]; }

        const float* Pc = &g_P[(size_t)col * NH + j8 * 8];
        const float* Pr = &g_P[(size_t)row * NH + 64 + j8 * 8];
        float4 a0 = *reinterpret_cast<const float4*>(Pc);
        float4 a1 = *reinterpret_cast<const float4*>(Pc + 4);
        float4 b0 = *reinterpret_cast<const float4*>(Pr);
        float4 b1 = *reinterpret_cast<const float4*>(Pr + 4);

        float p;
        p  = fmaxf(a0.x + b0.x + cv0.x, 0.f) * w20.x;
        p  = fmaf(fmaxf(a0.y + b0.y + cv0.y, 0.f), w20.y, p);
        p  = fmaf(fmaxf(a0.z + b0.z + cv0.z, 0.f), w20.z, p);
        p  = fmaf(fmaxf(a0.w + b0.w + cv0.w, 0.f), w20.w, p);
        p  = fmaf(fmaxf(a1.x + b1.x + cv1.x, 0.f), w21.x, p);
        p  = fmaf(fmaxf(a1.y + b1.y + cv1.y, 0.f), w21.y, p);
        p  = fmaf(fmaxf(a1.z + b1.z + cv1.z, 0.f), w21.z, p);
        p  = fmaf(fmaxf(a1.w + b1.w + cv1.w, 0.f), w21.w, p);

        p += __shfl_xor_sync(0xffffffffu, p, 4);
        p += __shfl_xor_sync(0xffffffffu, p, 2);
        p += __shfl_xor_sync(0xffffffffu, p, 1);

        if (j8 == 0) g_w[e] = p;
    }
}

// ---------------------------------------------------------------------------
// Kernel 3b: dense gate pass (tmp==1 fast path: no logs).
// ---------------------------------------------------------------------------
__global__ __launch_bounds__(256) void gate_kernel(const float* __restrict__ eps,
                                                   const float* __restrict__ tmp,
                                                   const float* __restrict__ b2,
                                                   float* __restrict__ out) {
    int i = blockIdx.x * blockDim.x + threadIdx.x;
    if (i * 4 >= N_EDGES) return;
    const float bias = 0.0001f, c1 = 1.f - 2.f * 0.0001f;
    float4 ev = *reinterpret_cast<const float4*>(&eps[i * 4]);
    float4 wv = *reinterpret_cast<const float4*>(&g_w[i * 4]);
    float t = tmp[0];
    float bb = b2[0];
    float e[4] = {fmaf(ev.x, c1, bias), fmaf(ev.y, c1, bias),
                  fmaf(ev.z, c1, bias), fmaf(ev.w, c1, bias)};
    float w[4] = {wv.x + bb, wv.y + bb, wv.z + bb, wv.w + bb};
    float o[4];
    if (t == 1.0f) {
        #pragma unroll
        for (int q = 0; q < 4; q++) {
            float s = __expf(-w[q]);
            o[q] = __fdividef(e[q], fmaf(s, 1.f - e[q], e[q]));
        }
    } else {
        float inv_t = __fdividef(1.f, t);
        #pragma unroll
        for (int q = 0; q < 4; q++) {
            float gate = (__logf(e[q]) - __logf(1.f - e[q]) + w[q]) * inv_t;
            o[q] = __fdividef(1.f, 1.f + __expf(-gate));
        }
    }
    *reinterpret_cast<float4*>(&out[i * 4]) = make_float4(o[0], o[1], o[2], o[3]);
}

// ---------------------------------------------------------------------------
// Inputs: 0:x 1:embed 2:edge_index 3:node_id 4:tmp 5:eps 6:W1 7:b1 8:W2 9:b2
// ---------------------------------------------------------------------------
extern "C" void kernel_launch(void* const* d_in, const int* in_sizes, int n_in,
                              void* d_out, int out_size) {
    const float* embed = (const float*)d_in[1];
    const void*  ei    = d_in[2];
    const int*   nid   = (const int*)d_in[3];
    const float* tmp   = (const float*)d_in[4];
    const float* eps   = (const float*)d_in[5];
    const float* W1    = (const float*)d_in[6];
    const float* b1    = (const float*)d_in[7];
    const float* W2    = (const float*)d_in[8];
    const float* b2    = (const float*)d_in[9];
    float* out = (float*)d_out;

    __nv_bfloat16 *eh, *el, *w1h, *w1l;
    cudaGetSymbolAddress((void**)&eh,  g_Eh);
    cudaGetSymbolAddress((void**)&el,  g_El);
    cudaGetSymbolAddress((void**)&w1h, g_W1h);
    cudaGetSymbolAddress((void**)&w1l, g_W1l);

    detect_kernel<<<1, 1>>>((const int*)ei);
    split_kernel<<<(N_NODES * EMB / 4 + 255) / 256, 256>>>(embed, eh, el, N_NODES * EMB / 4);
    split_kernel<<<(640 * 64 / 4 + 255) / 256, 256>>>(W1, w1h, w1l, 640 * 64 / 4);
    gemm_kernel<<<NTILES, 256>>>();
    cvec_kernel<<<1, 64>>>(embed, W1, b1, nid);
    edge_dot_kernel<<<1184, 256>>>(ei, W2);
    gate_kernel<<<(N_EDGES / 4 + 255) / 256, 256>>>(eps, tmp, b2, out);
}

// round 10
// speedup vs baseline: 1.3125x; 1.0346x over previous
#include <cuda_runtime.h>
#include <cuda_bf16.h>
#include <mma.h>
#include <cstdint>
using namespace nvcuda;

#define N_NODES   50000
#define EMB       320
#define HID       64
#define NH        128
#define N_EDGES   400000
#define NTILES    391          // ceil(50000/128)
#define KC        32
#define NCHUNK    (EMB / KC)   // 10

#define AP 40    // A smem pitch (bf16)
#define BP 136   // B smem pitch (bf16)

// Scratch (no allocations allowed)
__device__ __align__(16) float g_P[N_NODES * NH];
__device__ __align__(16) float g_w[N_EDGES];
__device__ __align__(16) float g_cvec[HID];
__device__ __align__(16) __nv_bfloat16 g_W1h[640 * 64];
__device__ __align__(16) __nv_bfloat16 g_W1l[640 * 64];
__device__ int g_idx64;

// ---------------------------------------------------------------------------
// Kernel 0: detect edge_index element width (int32 vs int64, little-endian).
// ---------------------------------------------------------------------------
__global__ void detect_kernel(const int* __restrict__ ei_raw) {
    int is64 = 1;
    #pragma unroll
    for (int i = 0; i < 32; i++)
        if (ei_raw[2 * i + 1] != 0) { is64 = 0; break; }
    g_idx64 = is64;
}

// ---------------------------------------------------------------------------
// Kernel S: W1[0:640] fp32 -> (hi, lo) bf16 split (tiny, one-shot).
// ---------------------------------------------------------------------------
__global__ __launch_bounds__(256) void splitW1_kernel(const float* __restrict__ W1) {
    int i = blockIdx.x * blockDim.x + threadIdx.x;
    if (i >= 640 * 64 / 4) return;
    float4 v = *reinterpret_cast<const float4*>(&W1[i * 4]);
    float a[4] = {v.x, v.y, v.z, v.w};
    __nv_bfloat16 h[4], l[4];
    #pragma unroll
    for (int q = 0; q < 4; q++) {
        h[q] = __float2bfloat16(a[q]);
        l[q] = __float2bfloat16(a[q] - __bfloat162float(h[q]));
    }
    *reinterpret_cast<uint2*>(&g_W1h[i * 4]) = *reinterpret_cast<uint2*>(h);
    *reinterpret_cast<uint2*>(&g_W1l[i * 4]) = *reinterpret_cast<uint2*>(l);
}

// ---------------------------------------------------------------------------
// Kernel 1: wmma bf16 3-term GEMM; A converted fp32->bf16(hi,lo) in the
// loader (hidden under HMMA), B pre-split. Register-prefetch double buffer.
//   P[v,0:64]  = embed[v] @ W1[0:320,:]
//   P[v,64:128]= embed[v] @ W1[320:640,:]
// acc += Ah*Bh + Ah*Bl + Al*Bh  (missing Al*Bl ~ 2^-16 rel).
// ---------------------------------------------------------------------------
__global__ __launch_bounds__(256, 2) void gemm_kernel(const float* __restrict__ embed) {
    __shared__ __nv_bfloat16 Ah[128][AP], Al[128][AP];
    __shared__ __nv_bfloat16 Bh[KC][BP],  Bl[KC][BP];

    const int tid = threadIdx.x;
    const int wid = tid >> 5;
    const int warp_m = wid & 1;
    const int warp_n = wid >> 1;
    const int m0 = blockIdx.x * 128;

    // A loader: row ar, k-base aks (16 contiguous floats per thread per chunk)
    const int ar  = tid >> 1;
    const int aks = (tid & 1) * 16;
    const int a_gm = m0 + ar;
    // B loader: 2 uint4 per buffer per thread
    const int bu4  = tid & 7;             // uint4 col (8 bf16)
    const int bhalf = (tid >> 3) & 1;
    const int bkr   = tid >> 4;           // k row 0..15 (+16 on second pass)

    wmma::fragment<wmma::accumulator, 16, 16, 16, float> acc[4][2];
    #pragma unroll
    for (int i = 0; i < 4; i++)
        #pragma unroll
        for (int j = 0; j < 2; j++)
            wmma::fill_fragment(acc[i][j], 0.f);

    float4 rA[4];
    uint4  rBh[2], rBl[2];

    auto loadA = [&](int k0) {
        if (a_gm < N_NODES) {
            const float* p = &embed[(size_t)a_gm * EMB + k0 + aks];
            #pragma unroll
            for (int q = 0; q < 4; q++)
                rA[q] = *reinterpret_cast<const float4*>(p + q * 4);
        } else {
            #pragma unroll
            for (int q = 0; q < 4; q++)
                rA[q] = make_float4(0.f, 0.f, 0.f, 0.f);
        }
    };
    auto loadB = [&](int k0) {
        #pragma unroll
        for (int p = 0; p < 2; p++) {
            size_t off = (size_t)(bhalf * 320 + k0 + bkr + p * 16) * 64 + bu4 * 8;
            rBh[p] = *reinterpret_cast<const uint4*>(&g_W1h[off]);
            rBl[p] = *reinterpret_cast<const uint4*>(&g_W1l[off]);
        }
    };
    auto stsA = [&]() {
        #pragma unroll
        for (int q = 0; q < 4; q++) {
            float a[4] = {rA[q].x, rA[q].y, rA[q].z, rA[q].w};
            __nv_bfloat16 h[4], l[4];
            #pragma unroll
            for (int i = 0; i < 4; i++) {
                h[i] = __float2bfloat16(a[i]);
                l[i] = __float2bfloat16(a[i] - __bfloat162float(h[i]));
            }
            *reinterpret_cast<uint2*>(&Ah[ar][aks + q * 4]) = *reinterpret_cast<uint2*>(h);
            *reinterpret_cast<uint2*>(&Al[ar][aks + q * 4]) = *reinterpret_cast<uint2*>(l);
        }
    };
    auto stsB = [&]() {
        #pragma unroll
        for (int p = 0; p < 2; p++) {
            *reinterpret_cast<uint4*>(&Bh[bkr + p * 16][bhalf * 64 + bu4 * 8]) = rBh[p];
            *reinterpret_cast<uint4*>(&Bl[bkr + p * 16][bhalf * 64 + bu4 * 8]) = rBl[p];
        }
    };

    loadA(0);
    loadB(0);
    stsA();
    stsB();
    __syncthreads();

    for (int c = 0; c < NCHUNK; c++) {
        if (c + 1 < NCHUNK) {
            loadA((c + 1) * KC);
            loadB((c + 1) * KC);
        }

        #pragma unroll
        for (int ks = 0; ks < 2; ks++) {
            wmma::fragment<wmma::matrix_b, 16, 16, 16, __nv_bfloat16, wmma::row_major> bh[2], bl[2];
            #pragma unroll
            for (int j = 0; j < 2; j++) {
                wmma::load_matrix_sync(bh[j], &Bh[ks * 16][warp_n * 32 + j * 16], BP);
                wmma::load_matrix_sync(bl[j], &Bl[ks * 16][warp_n * 32 + j * 16], BP);
            }
            #pragma unroll
            for (int i = 0; i < 4; i++) {
                wmma::fragment<wmma::matrix_a, 16, 16, 16, __nv_bfloat16, wmma::row_major> fah, fal;
                wmma::load_matrix_sync(fah, &Ah[warp_m * 64 + i * 16][ks * 16], AP);
                wmma::load_matrix_sync(fal, &Al[warp_m * 64 + i * 16][ks * 16], AP);
                #pragma unroll
                for (int j = 0; j < 2; j++) {
                    wmma::mma_sync(acc[i][j], fah, bh[j], acc[i][j]);
                    wmma::mma_sync(acc[i][j], fah, bl[j], acc[i][j]);
                    wmma::mma_sync(acc[i][j], fal, bh[j], acc[i][j]);
                }
            }
        }
        __syncthreads();
        if (c + 1 < NCHUNK) {
            stsA();
            stsB();
            __syncthreads();
        }
    }

    #pragma unroll
    for (int i = 0; i < 4; i++) {
        int gm = m0 + warp_m * 64 + i * 16;
        if (gm < N_NODES) {
            #pragma unroll
            for (int j = 0; j < 2; j++)
                wmma::store_matrix_sync(&g_P[(size_t)gm * NH + warp_n * 32 + j * 16],
                                        acc[i][j], NH, wmma::mem_row_major);
        }
    }
}

// ---------------------------------------------------------------------------
// Kernel 2: cvec[j] = b1[j] + embed[node_id] @ W1[640:960, j]   (exact fp32)
// ---------------------------------------------------------------------------
__global__ void cvec_kernel(const float* __restrict__ embed,
                            const float* __restrict__ W1,
                            const float* __restrict__ b1,
                            const int*   __restrict__ nid) {
    int j = threadIdx.x;
    int n = nid[0];
    const float* er = &embed[(size_t)n * EMB];
    float s = b1[j];
    #pragma unroll 4
    for (int k = 0; k < EMB; k++)
        s = fmaf(er[k], W1[(640 + k) * 64 + j], s);
    g_cvec[j] = s;
}

// ---------------------------------------------------------------------------
// Kernel 3a: gather + dot (no transcendentals). 8 lanes/edge, 4 edges/warp.
// ---------------------------------------------------------------------------
__global__ __launch_bounds__(256) void edge_dot_kernel(const void* __restrict__ ei_raw,
                                                       const float* __restrict__ W2) {
    const int lane = threadIdx.x & 31;
    const int sub  = lane >> 3;
    const int j8   = lane & 7;
    const int warpGlobal = (blockIdx.x * blockDim.x + threadIdx.x) >> 5;
    const int nWarps = (gridDim.x * blockDim.x) >> 5;

    const float4 cv0 = *reinterpret_cast<const float4*>(&g_cvec[j8 * 8]);
    const float4 cv1 = *reinterpret_cast<const float4*>(&g_cvec[j8 * 8 + 4]);
    const float4 w20 = *reinterpret_cast<const float4*>(&W2[j8 * 8]);
    const float4 w21 = *reinterpret_cast<const float4*>(&W2[j8 * 8 + 4]);
    const int is64 = g_idx64;
    const long long* e64 = (const long long*)ei_raw;
    const int*       e32 = (const int*)ei_raw;

    for (int e = warpGlobal * 4 + sub; e < N_EDGES; e += nWarps * 4) {
        int col, row;
        if (is64) { col = (int)e64[e]; row = (int)e64[N_EDGES + e]; }
        else      { col = e32[e];      row = e32[N_EDGES + e]; }

        const float* Pc = &g_P[(size_t)col * NH + j8 * 8];
        const float* Pr = &g_P[(size_t)row * NH + 64 + j8 * 8];
        float4 a0 = *reinterpret_cast<const float4*>(Pc);
        float4 a1 = *reinterpret_cast<const float4*>(Pc + 4);
        float4 b0 = *reinterpret_cast<const float4*>(Pr);
        float4 b1 = *reinterpret_cast<const float4*>(Pr + 4);

        float p;
        p  = fmaxf(a0.x + b0.x + cv0.x, 0.f) * w20.x;
        p  = fmaf(fmaxf(a0.y + b0.y + cv0.y, 0.f), w20.y, p);
        p  = fmaf(fmaxf(a0.z + b0.z + cv0.z, 0.f), w20.z, p);
        p  = fmaf(fmaxf(a0.w + b0.w + cv0.w, 0.f), w20.w, p);
        p  = fmaf(fmaxf(a1.x + b1.x + cv1.x, 0.f), w21.x, p);
        p  = fmaf(fmaxf(a1.y + b1.y + cv1.y, 0.f), w21.y, p);
        p  = fmaf(fmaxf(a1.z + b1.z + cv1.z, 0.f), w21.z, p);
        p  = fmaf(fmaxf(a1.w + b1.w + cv1.w, 0.f), w21.w, p);

        p += __shfl_xor_sync(0xffffffffu, p, 4);
        p += __shfl_xor_sync(0xffffffffu, p, 2);
        p += __shfl_xor_sync(0xffffffffu, p, 1);

        if (j8 == 0) g_w[e] = p;
    }
}

// ---------------------------------------------------------------------------
// Kernel 3b: dense gate pass (tmp==1 fast path: no logs).
// ---------------------------------------------------------------------------
__global__ __launch_bounds__(256) void gate_kernel(const float* __restrict__ eps,
                                                   const float* __restrict__ tmp,
                                                   const float* __restrict__ b2,
                                                   float* __restrict__ out) {
    int i = blockIdx.x * blockDim.x + threadIdx.x;
    if (i * 4 >= N_EDGES) return;
    const float bias = 0.0001f, c1 = 1.f - 2.f * 0.0001f;
    float4 ev = *reinterpret_cast<const float4*>(&eps[i * 4]);
    float4 wv = *reinterpret_cast<const float4*>(&g_w[i * 4]);
    float t = tmp[0];
    float bb = b2[0];
    float e[4] = {fmaf(ev.x, c1, bias), fmaf(ev.y, c1, bias),
                  fmaf(ev.z, c1, bias), fmaf(ev.w, c1, bias)};
    float w[4] = {wv.x + bb, wv.y + bb, wv.z + bb, wv.w + bb};
    float o[4];
    if (t == 1.0f) {
        #pragma unroll
        for (int q = 0; q < 4; q++) {
            float s = __expf(-w[q]);
            o[q] = __fdividef(e[q], fmaf(s, 1.f - e[q], e[q]));
        }
    } else {
        float inv_t = __fdividef(1.f, t);
        #pragma unroll
        for (int q = 0; q < 4; q++) {
            float gate = (__logf(e[q]) - __logf(1.f - e[q]) + w[q]) * inv_t;
            o[q] = __fdividef(1.f, 1.f + __expf(-gate));
        }
    }
    *reinterpret_cast<float4*>(&out[i * 4]) = make_float4(o[0], o[1], o[2], o[3]);
}

// ---------------------------------------------------------------------------
// Inputs: 0:x 1:embed 2:edge_index 3:node_id 4:tmp 5:eps 6:W1 7:b1 8:W2 9:b2
// ---------------------------------------------------------------------------
extern "C" void kernel_launch(void* const* d_in, const int* in_sizes, int n_in,
                              void* d_out, int out_size) {
    const float* embed = (const float*)d_in[1];
    const void*  ei    = d_in[2];
    const int*   nid   = (const int*)d_in[3];
    const float* tmp   = (const float*)d_in[4];
    const float* eps   = (const float*)d_in[5];
    const float* W1    = (const float*)d_in[6];
    const float* b1    = (const float*)d_in[7];
    const float* W2    = (const float*)d_in[8];
    const float* b2    = (const float*)d_in[9];
    float* out = (float*)d_out;

    detect_kernel<<<1, 1>>>((const int*)ei);
    splitW1_kernel<<<(640 * 64 / 4 + 255) / 256, 256>>>(W1);
    gemm_kernel<<<NTILES, 256>>>(embed);
    cvec_kernel<<<1, 64>>>(embed, W1, b1, nid);
    edge_dot_kernel<<<1184, 256>>>(ei, W2);
    gate_kernel<<<(N_EDGES / 4 + 255) / 256, 256>>>(eps, tmp, b2, out);
}

// round 11
// speedup vs baseline: 1.7485x; 1.3322x over previous
#include <cuda_runtime.h>
#include <cuda_bf16.h>
#include <mma.h>
#include <cstdint>
using namespace nvcuda;

#define N_NODES   50000
#define EMB       320
#define HID       64
#define NH        128
#define N_EDGES   400000
#define NTILES    391          // ceil(50000/128)
#define KC        32
#define NCHUNK    (EMB / KC)   // 10

#define AP 40    // A smem pitch (bf16)
#define BP 136   // B smem pitch (bf16)

// Scratch (no allocations allowed)
__device__ __align__(16) float g_P[N_NODES * NH];
__device__ __align__(16) float g_w[N_EDGES];
__device__ __align__(16) float g_cvec[HID];
__device__ __align__(16) __nv_bfloat16 g_W1h[640 * 64];
__device__ __align__(16) __nv_bfloat16 g_W1l[640 * 64];
__device__ int g_idx64;

// ---------------------------------------------------------------------------
// Kernel 0: detect edge_index element width (int32 vs int64, little-endian).
// ---------------------------------------------------------------------------
__global__ void detect_kernel(const int* __restrict__ ei_raw) {
    int is64 = 1;
    #pragma unroll
    for (int i = 0; i < 32; i++)
        if (ei_raw[2 * i + 1] != 0) { is64 = 0; break; }
    g_idx64 = is64;
}

// ---------------------------------------------------------------------------
// Kernel S: W1[0:640] fp32 -> (hi, lo) bf16 split (tiny, one-shot).
// ---------------------------------------------------------------------------
__global__ __launch_bounds__(256) void splitW1_kernel(const float* __restrict__ W1) {
    int i = blockIdx.x * blockDim.x + threadIdx.x;
    if (i >= 640 * 64 / 4) return;
    float4 v = *reinterpret_cast<const float4*>(&W1[i * 4]);
    float a[4] = {v.x, v.y, v.z, v.w};
    __nv_bfloat16 h[4], l[4];
    #pragma unroll
    for (int q = 0; q < 4; q++) {
        h[q] = __float2bfloat16(a[q]);
        l[q] = __float2bfloat16(a[q] - __bfloat162float(h[q]));
    }
    *reinterpret_cast<uint2*>(&g_W1h[i * 4]) = *reinterpret_cast<uint2*>(h);
    *reinterpret_cast<uint2*>(&g_W1l[i * 4]) = *reinterpret_cast<uint2*>(l);
}

// ---------------------------------------------------------------------------
// Kernel 1: wmma bf16 3-term GEMM; A converted fp32->bf16(hi,lo) in the
// loader (hidden under HMMA), B pre-split. Register-prefetch double buffer.
//   P[v,0:64]  = embed[v] @ W1[0:320,:]
//   P[v,64:128]= embed[v] @ W1[320:640,:]
// acc += Ah*Bh + Ah*Bl + Al*Bh  (missing Al*Bl ~ 2^-16 rel).
// ---------------------------------------------------------------------------
__global__ __launch_bounds__(256, 2) void gemm_kernel(const float* __restrict__ embed) {
    __shared__ __nv_bfloat16 Ah[128][AP], Al[128][AP];
    __shared__ __nv_bfloat16 Bh[KC][BP],  Bl[KC][BP];

    const int tid = threadIdx.x;
    const int wid = tid >> 5;
    const int warp_m = wid & 1;
    const int warp_n = wid >> 1;
    const int m0 = blockIdx.x * 128;

    const int ar  = tid >> 1;
    const int aks = (tid & 1) * 16;
    const int a_gm = m0 + ar;
    const int bu4  = tid & 7;
    const int bhalf = (tid >> 3) & 1;
    const int bkr   = tid >> 4;

    wmma::fragment<wmma::accumulator, 16, 16, 16, float> acc[4][2];
    #pragma unroll
    for (int i = 0; i < 4; i++)
        #pragma unroll
        for (int j = 0; j < 2; j++)
            wmma::fill_fragment(acc[i][j], 0.f);

    float4 rA[4];
    uint4  rBh[2], rBl[2];

    auto loadA = [&](int k0) {
        if (a_gm < N_NODES) {
            const float* p = &embed[(size_t)a_gm * EMB + k0 + aks];
            #pragma unroll
            for (int q = 0; q < 4; q++)
                rA[q] = *reinterpret_cast<const float4*>(p + q * 4);
        } else {
            #pragma unroll
            for (int q = 0; q < 4; q++)
                rA[q] = make_float4(0.f, 0.f, 0.f, 0.f);
        }
    };
    auto loadB = [&](int k0) {
        #pragma unroll
        for (int p = 0; p < 2; p++) {
            size_t off = (size_t)(bhalf * 320 + k0 + bkr + p * 16) * 64 + bu4 * 8;
            rBh[p] = *reinterpret_cast<const uint4*>(&g_W1h[off]);
            rBl[p] = *reinterpret_cast<const uint4*>(&g_W1l[off]);
        }
    };
    auto stsA = [&]() {
        #pragma unroll
        for (int q = 0; q < 4; q++) {
            float a[4] = {rA[q].x, rA[q].y, rA[q].z, rA[q].w};
            __nv_bfloat16 h[4], l[4];
            #pragma unroll
            for (int i = 0; i < 4; i++) {
                h[i] = __float2bfloat16(a[i]);
                l[i] = __float2bfloat16(a[i] - __bfloat162float(h[i]));
            }
            *reinterpret_cast<uint2*>(&Ah[ar][aks + q * 4]) = *reinterpret_cast<uint2*>(h);
            *reinterpret_cast<uint2*>(&Al[ar][aks + q * 4]) = *reinterpret_cast<uint2*>(l);
        }
    };
    auto stsB = [&]() {
        #pragma unroll
        for (int p = 0; p < 2; p++) {
            *reinterpret_cast<uint4*>(&Bh[bkr + p * 16][bhalf * 64 + bu4 * 8]) = rBh[p];
            *reinterpret_cast<uint4*>(&Bl[bkr + p * 16][bhalf * 64 + bu4 * 8]) = rBl[p];
        }
    };

    loadA(0);
    loadB(0);
    stsA();
    stsB();
    __syncthreads();

    for (int c = 0; c < NCHUNK; c++) {
        if (c + 1 < NCHUNK) {
            loadA((c + 1) * KC);
            loadB((c + 1) * KC);
        }

        #pragma unroll
        for (int ks = 0; ks < 2; ks++) {
            wmma::fragment<wmma::matrix_b, 16, 16, 16, __nv_bfloat16, wmma::row_major> bh[2], bl[2];
            #pragma unroll
            for (int j = 0; j < 2; j++) {
                wmma::load_matrix_sync(bh[j], &Bh[ks * 16][warp_n * 32 + j * 16], BP);
                wmma::load_matrix_sync(bl[j], &Bl[ks * 16][warp_n * 32 + j * 16], BP);
            }
            #pragma unroll
            for (int i = 0; i < 4; i++) {
                wmma::fragment<wmma::matrix_a, 16, 16, 16, __nv_bfloat16, wmma::row_major> fah, fal;
                wmma::load_matrix_sync(fah, &Ah[warp_m * 64 + i * 16][ks * 16], AP);
                wmma::load_matrix_sync(fal, &Al[warp_m * 64 + i * 16][ks * 16], AP);
                #pragma unroll
                for (int j = 0; j < 2; j++) {
                    wmma::mma_sync(acc[i][j], fah, bh[j], acc[i][j]);
                    wmma::mma_sync(acc[i][j], fah, bl[j], acc[i][j]);
                    wmma::mma_sync(acc[i][j], fal, bh[j], acc[i][j]);
                }
            }
        }
        __syncthreads();
        if (c + 1 < NCHUNK) {
            stsA();
            stsB();
            __syncthreads();
        }
    }

    #pragma unroll
    for (int i = 0; i < 4; i++) {
        int gm = m0 + warp_m * 64 + i * 16;
        if (gm < N_NODES) {
            #pragma unroll
            for (int j = 0; j < 2; j++)
                wmma::store_matrix_sync(&g_P[(size_t)gm * NH + warp_n * 32 + j * 16],
                                        acc[i][j], NH, wmma::mem_row_major);
        }
    }
}

// ---------------------------------------------------------------------------
// Kernel 2: cvec[j] = b1[j] + embed[node_id] @ W1[640:960, j]  — k-parallel.
// 512 threads: j = tid & 63, segment s = tid >> 6 (8 segs x 40 k each).
// 40 independent load+FMA pairs per thread (MLP-bound), smem tree-reduce.
// ---------------------------------------------------------------------------
__global__ __launch_bounds__(512) void cvec_kernel(const float* __restrict__ embed,
                                                   const float* __restrict__ W1,
                                                   const float* __restrict__ b1,
                                                   const int*   __restrict__ nid) {
    __shared__ float red[8][64];
    const int j = threadIdx.x & 63;
    const int s = threadIdx.x >> 6;          // 0..7
    const int n = nid[0];
    const float* er = &embed[(size_t)n * EMB];

    float sum = 0.f;
    #pragma unroll
    for (int q = 0; q < 40; q++) {
        int k = s * 40 + q;
        sum = fmaf(er[k], W1[(640 + k) * 64 + j], sum);
    }
    red[s][j] = sum;
    __syncthreads();
    if (s < 4) red[s][j] += red[s + 4][j];
    __syncthreads();
    if (s < 2) red[s][j] += red[s + 2][j];
    __syncthreads();
    if (s == 0) g_cvec[j] = red[0][j] + red[1][j] + b1[j];
}

// ---------------------------------------------------------------------------
// Kernel 3a: gather + dot (no transcendentals). 8 lanes/edge, 4 edges/warp.
// ---------------------------------------------------------------------------
__global__ __launch_bounds__(256) void edge_dot_kernel(const void* __restrict__ ei_raw,
                                                       const float* __restrict__ W2) {
    const int lane = threadIdx.x & 31;
    const int sub  = lane >> 3;
    const int j8   = lane & 7;
    const int warpGlobal = (blockIdx.x * blockDim.x + threadIdx.x) >> 5;
    const int nWarps = (gridDim.x * blockDim.x) >> 5;

    const float4 cv0 = *reinterpret_cast<const float4*>(&g_cvec[j8 * 8]);
    const float4 cv1 = *reinterpret_cast<const float4*>(&g_cvec[j8 * 8 + 4]);
    const float4 w20 = *reinterpret_cast<const float4*>(&W2[j8 * 8]);
    const float4 w21 = *reinterpret_cast<const float4*>(&W2[j8 * 8 + 4]);
    const int is64 = g_idx64;
    const long long* e64 = (const long long*)ei_raw;
    const int*       e32 = (const int*)ei_raw;

    for (int e = warpGlobal * 4 + sub; e < N_EDGES; e += nWarps * 4) {
        int col, row;
        if (is64) { col = (int)e64[e]; row = (int)e64[N_EDGES + e]; }
        else      { col = e32[e];      row = e32[N_EDGES + e]; }

        const float* Pc = &g_P[(size_t)col * NH + j8 * 8];
        const float* Pr = &g_P[(size_t)row * NH + 64 + j8 * 8];
        float4 a0 = *reinterpret_cast<const float4*>(Pc);
        float4 a1 = *reinterpret_cast<const float4*>(Pc + 4);
        float4 b0 = *reinterpret_cast<const float4*>(Pr);
        float4 b1 = *reinterpret_cast<const float4*>(Pr + 4);

        float p;
        p  = fmaxf(a0.x + b0.x + cv0.x, 0.f) * w20.x;
        p  = fmaf(fmaxf(a0.y + b0.y + cv0.y, 0.f), w20.y, p);
        p  = fmaf(fmaxf(a0.z + b0.z + cv0.z, 0.f), w20.z, p);
        p  = fmaf(fmaxf(a0.w + b0.w + cv0.w, 0.f), w20.w, p);
        p  = fmaf(fmaxf(a1.x + b1.x + cv1.x, 0.f), w21.x, p);
        p  = fmaf(fmaxf(a1.y + b1.y + cv1.y, 0.f), w21.y, p);
        p  = fmaf(fmaxf(a1.z + b1.z + cv1.z, 0.f), w21.z, p);
        p  = fmaf(fmaxf(a1.w + b1.w + cv1.w, 0.f), w21.w, p);

        p += __shfl_xor_sync(0xffffffffu, p, 4);
        p += __shfl_xor_sync(0xffffffffu, p, 2);
        p += __shfl_xor_sync(0xffffffffu, p, 1);

        if (j8 == 0) g_w[e] = p;
    }
}

// ---------------------------------------------------------------------------
// Kernel 3b: dense gate pass (tmp==1 fast path: no logs).
// ---------------------------------------------------------------------------
__global__ __launch_bounds__(256) void gate_kernel(const float* __restrict__ eps,
                                                   const float* __restrict__ tmp,
                                                   const float* __restrict__ b2,
                                                   float* __restrict__ out) {
    int i = blockIdx.x * blockDim.x + threadIdx.x;
    if (i * 4 >= N_EDGES) return;
    const float bias = 0.0001f, c1 = 1.f - 2.f * 0.0001f;
    float4 ev = *reinterpret_cast<const float4*>(&eps[i * 4]);
    float4 wv = *reinterpret_cast<const float4*>(&g_w[i * 4]);
    float t = tmp[0];
    float bb = b2[0];
    float e[4] = {fmaf(ev.x, c1, bias), fmaf(ev.y, c1, bias),
                  fmaf(ev.z, c1, bias), fmaf(ev.w, c1, bias)};
    float w[4] = {wv.x + bb, wv.y + bb, wv.z + bb, wv.w + bb};
    float o[4];
    if (t == 1.0f) {
        #pragma unroll
        for (int q = 0; q < 4; q++) {
            float s = __expf(-w[q]);
            o[q] = __fdividef(e[q], fmaf(s, 1.f - e[q], e[q]));
        }
    } else {
        float inv_t = __fdividef(1.f, t);
        #pragma unroll
        for (int q = 0; q < 4; q++) {
            float gate = (__logf(e[q]) - __logf(1.f - e[q]) + w[q]) * inv_t;
            o[q] = __fdividef(1.f, 1.f + __expf(-gate));
        }
    }
    *reinterpret_cast<float4*>(&out[i * 4]) = make_float4(o[0], o[1], o[2], o[3]);
}

// ---------------------------------------------------------------------------
// Inputs: 0:x 1:embed 2:edge_index 3:node_id 4:tmp 5:eps 6:W1 7:b1 8:W2 9:b2
// ---------------------------------------------------------------------------
extern "C" void kernel_launch(void* const* d_in, const int* in_sizes, int n_in,
                              void* d_out, int out_size) {
    const float* embed = (const float*)d_in[1];
    const void*  ei    = d_in[2];
    const int*   nid   = (const int*)d_in[3];
    const float* tmp   = (const float*)d_in[4];
    const float* eps   = (const float*)d_in[5];
    const float* W1    = (const float*)d_in[6];
    const float* b1    = (const float*)d_in[7];
    const float* W2    = (const float*)d_in[8];
    const float* b2    = (const float*)d_in[9];
    float* out = (float*)d_out;

    detect_kernel<<<1, 1>>>((const int*)ei);
    splitW1_kernel<<<(640 * 64 / 4 + 255) / 256, 256>>>(W1);
    cvec_kernel<<<1, 512>>>(embed, W1, b1, nid);
    gemm_kernel<<<NTILES, 256>>>(embed);
    edge_dot_kernel<<<1184, 256>>>(ei, W2);
    gate_kernel<<<(N_EDGES / 4 + 255) / 256, 256>>>(eps, tmp, b2, out);
}